// round 6
// baseline (speedup 1.0000x reference)
#include <cuda_runtime.h>
#include <cuda_bf16.h>
#include <cstdint>

// ============================================================================
// QuantizedLoRALinear on GB300 (sm_103a harness, PTX target sm_103 -> NO
// tcgen05 available; use mma.sync HMMA path).
//
//   out[8192,4096] = (x*s)[8192,4096] @ Wq[4096,4096]^T
//                  + 2*(x @ A^T)[8192,16] @ B[4096,16]^T
//
// Scheme:
//   Wq (ints in [-128,127]) -> bf16 EXACT.
//   xs = x*s split into bf16 hi+lo -> 2 HMMA passes, fp32 register acc.
//   LoRA folded in as one extra K-chunk (A-slot <- bf16(2*x@A^T) padded to
//   64 cols, B-slot <- bf16(lora_B) padded). Epilogue = pure store.
//
// GEMM: CTA tile 128x256, BK=64 (128B rows, SW128 swizzle), 3-stage cp.async
//       pipeline, 8 warps (2M x 4N), warp tile 64x64, mma.sync.m16n8k16.
// ============================================================================

#define MDIM 8192
#define NDIM 4096
#define KDIM 4096

#define TBM 128
#define TBN 256
#define TBK 64
#define NKW (KDIM / TBK)   // 64 weight chunks
#define NK  (NKW + 1)      // +1 LoRA chunk

#define STAGE_BYTES 65536  // A_hi 16K | A_lo 16K | B 32K
#define OFF_AHI 0
#define OFF_ALO 16384
#define OFF_B   32768
#define SMEM_ALLOC (3 * STAGE_BYTES + 1024)

// ---------------- scratch (__device__ globals; no allocations) --------------
__device__ __nv_bfloat16 g_xhi[(size_t)MDIM * KDIM];  // 64 MB
__device__ __nv_bfloat16 g_xlo[(size_t)MDIM * KDIM];  // 64 MB
__device__ __nv_bfloat16 g_wq [(size_t)NDIM * KDIM];  // 32 MB
__device__ __nv_bfloat16 g_t2a[(size_t)MDIM * 64];    // 1 MB   (2*x@A^T, cols 16..63 = 0)
__device__ __nv_bfloat16 g_bb [(size_t)NDIM * 64];    // 0.5 MB (lora_B,   cols 16..63 = 0)

// ---------------- PTX helpers ----------------------------------------------
__device__ __forceinline__ uint32_t smem_u32(const void* p) {
    uint32_t a;
    asm("{ .reg .u64 t; cvta.to.shared.u64 t, %1; cvt.u32.u64 %0, t; }"
        : "=r"(a) : "l"(p));
    return a;
}

#define SWZ128(off) ((off) ^ (((off) >> 3) & 0x70))

__device__ __forceinline__ void cpa16(uint32_t dst, const void* src) {
    asm volatile("cp.async.cg.shared.global [%0], [%1], 16;\n" :: "r"(dst), "l"(src));
}
__device__ __forceinline__ void cpa_commit() {
    asm volatile("cp.async.commit_group;\n" ::: "memory");
}
template <int N> __device__ __forceinline__ void cpa_wait() {
    asm volatile("cp.async.wait_group %0;\n" :: "n"(N) : "memory");
}

__device__ __forceinline__ void ldsm_x4(uint32_t* r, uint32_t addr) {
    asm volatile("ldmatrix.sync.aligned.m8n8.x4.shared.b16 {%0,%1,%2,%3}, [%4];"
                 : "=r"(r[0]), "=r"(r[1]), "=r"(r[2]), "=r"(r[3]) : "r"(addr));
}

__device__ __forceinline__ void mma16816(float* c, const uint32_t* a,
                                         uint32_t b0, uint32_t b1) {
    asm volatile(
        "mma.sync.aligned.m16n8k16.row.col.f32.bf16.bf16.f32 "
        "{%0,%1,%2,%3}, {%4,%5,%6,%7}, {%8,%9}, {%0,%1,%2,%3};"
        : "+f"(c[0]), "+f"(c[1]), "+f"(c[2]), "+f"(c[3])
        : "r"(a[0]), "r"(a[1]), "r"(a[2]), "r"(a[3]), "r"(b0), "r"(b1));
}

// ---------------- prep kernels ----------------------------------------------

// W int32 -> bf16 (exact). 4 elems/thread.
__global__ void k_convert_w(const int* __restrict__ w) {
    size_t i = ((size_t)blockIdx.x * blockDim.x + threadIdx.x) * 4;
    int4 v = *reinterpret_cast<const int4*>(w + i);
    __nv_bfloat162* dst = reinterpret_cast<__nv_bfloat162*>(g_wq + i);
    dst[0] = __halves2bfloat162(__float2bfloat16_rn((float)v.x),
                                __float2bfloat16_rn((float)v.y));
    dst[1] = __halves2bfloat162(__float2bfloat16_rn((float)v.z),
                                __float2bfloat16_rn((float)v.w));
}

// xs = x*s; hi = bf16(xs); lo = bf16(xs - hi). 4 elems/thread.
__global__ void k_split_x(const float* __restrict__ x, const float* __restrict__ sp) {
    const float s = *sp;
    size_t i = ((size_t)blockIdx.x * blockDim.x + threadIdx.x) * 4;
    float4 v = *reinterpret_cast<const float4*>(x + i);
    float xs[4] = {v.x * s, v.y * s, v.z * s, v.w * s};
    __nv_bfloat16 hi[4], lo[4];
#pragma unroll
    for (int j = 0; j < 4; j++) {
        hi[j] = __float2bfloat16_rn(xs[j]);
        lo[j] = __float2bfloat16_rn(xs[j] - __bfloat162float(hi[j]));
    }
    __nv_bfloat162* dh = reinterpret_cast<__nv_bfloat162*>(g_xhi + i);
    __nv_bfloat162* dl = reinterpret_cast<__nv_bfloat162*>(g_xlo + i);
    dh[0] = __halves2bfloat162(hi[0], hi[1]);
    dh[1] = __halves2bfloat162(hi[2], hi[3]);
    dl[0] = __halves2bfloat162(lo[0], lo[1]);
    dl[1] = __halves2bfloat162(lo[2], lo[3]);
}

// t2a[m][r] = bf16(2 * sum_k x[m][k]*A[r][k]) for r<16, 0 for r in [16,64).
__global__ __launch_bounds__(256) void k_lora_t(const float* __restrict__ x,
                                                const float* __restrict__ A) {
    __shared__ float sA[16 * 512];
    __shared__ float sT[8][16];
    const int tid = threadIdx.x;
    const int w = tid >> 5, l = tid & 31;
    const int m = blockIdx.x * 8 + w;

    float acc[16];
#pragma unroll
    for (int r = 0; r < 16; r++) acc[r] = 0.f;

    for (int kc = 0; kc < 8; kc++) {
        __syncthreads();
#pragma unroll
        for (int i = 0; i < 8; i++) {
            int v = tid + 256 * i;          // float4 index, 0..2047
            int r = v >> 7, c4 = v & 127;
            *reinterpret_cast<float4*>(&sA[r * 512 + c4 * 4]) =
                *reinterpret_cast<const float4*>(A + (size_t)r * KDIM + kc * 512 + c4 * 4);
        }
        __syncthreads();
#pragma unroll
        for (int i = 0; i < 16; i++) {
            int k = l + i * 32;
            float xv = x[(size_t)m * KDIM + kc * 512 + k];
#pragma unroll
            for (int r = 0; r < 16; r++) acc[r] += xv * sA[r * 512 + k];
        }
    }
#pragma unroll
    for (int r = 0; r < 16; r++) {
        float v = acc[r];
#pragma unroll
        for (int off = 16; off; off >>= 1) v += __shfl_xor_sync(0xffffffffu, v, off);
        acc[r] = v;
    }
    if (l == 0) {
#pragma unroll
        for (int r = 0; r < 16; r++) sT[w][r] = acc[r];
    }
    __syncwarp();
    float tv = (l < 16) ? sT[w][l] : 0.f;
    g_t2a[(size_t)m * 64 + l]      = __float2bfloat16_rn(2.0f * tv);
    g_t2a[(size_t)m * 64 + 32 + l] = __float2bfloat16_rn(0.f);
}

// bb[n][r] = bf16(B[n][r]) for r<16 else 0.
__global__ void k_pad_b(const float* __restrict__ B) {
    int i = blockIdx.x * blockDim.x + threadIdx.x;  // 0 .. 4096*64-1
    int n = i >> 6, r = i & 63;
    float v = (r < 16) ? B[n * 16 + r] : 0.f;
    g_bb[i] = __float2bfloat16_rn(v);
}

// ---------------- main HMMA GEMM ---------------------------------------------

__global__ __launch_bounds__(256, 1) void k_gemm(float* __restrict__ out) {
    extern __shared__ char smem_raw[];
    const uint32_t sb = (smem_u32(smem_raw) + 1023u) & ~1023u;  // 1024-aligned
    const int tid = threadIdx.x;
    const int wid = tid >> 5;
    const int lid = tid & 31;
    const int wm = wid & 1;    // 2 warps along M
    const int wn = wid >> 1;   // 4 warps along N

    // 8-wide M supertiles for L2 locality: 128 bids per group = 8 M x 16 N.
    const int bid = blockIdx.x;
    const int grp = bid >> 7, loc = bid & 127;
    const int m0 = (grp * 8 + (loc & 7)) * TBM;
    const int n0 = (loc >> 3) * TBN;

    float acc[4][8][4];
#pragma unroll
    for (int i = 0; i < 4; i++)
#pragma unroll
        for (int j = 0; j < 8; j++)
#pragma unroll
            for (int t = 0; t < 4; t++) acc[i][j][t] = 0.f;

    // cooperative swizzled loader for K-chunk k into its stage slot
    auto load_chunk = [&](int k) {
        const uint32_t slot = sb + (uint32_t)(k % 3) * STAGE_BYTES;
        if (k < NKW) {
            const __nv_bfloat16* srcA = g_xhi + (size_t)m0 * KDIM + (size_t)k * TBK;
            const __nv_bfloat16* srcL = g_xlo + (size_t)m0 * KDIM + (size_t)k * TBK;
            const __nv_bfloat16* srcB = g_wq  + (size_t)n0 * KDIM + (size_t)k * TBK;
#pragma unroll
            for (int i = 0; i < 4; i++) {                   // A tiles: 1024 x 16B
                int c = tid + 256 * i;
                int row = c >> 3, c16 = c & 7;
                uint32_t so = SWZ128((uint32_t)(row * 128 + c16 * 16));
                cpa16(slot + OFF_AHI + so, srcA + (size_t)row * KDIM + c16 * 8);
                cpa16(slot + OFF_ALO + so, srcL + (size_t)row * KDIM + c16 * 8);
            }
#pragma unroll
            for (int i = 0; i < 8; i++) {                   // B tile: 2048 x 16B
                int c = tid + 256 * i;
                int row = c >> 3, c16 = c & 7;
                uint32_t so = SWZ128((uint32_t)(row * 128 + c16 * 16));
                cpa16(slot + OFF_B + so, srcB + (size_t)row * KDIM + c16 * 8);
            }
        } else {
            // LoRA chunk: rows are 64 bf16 = 128B, zero-padded beyond r=16
            const __nv_bfloat16* srcA = g_t2a + (size_t)m0 * 64;
            const __nv_bfloat16* srcB = g_bb  + (size_t)n0 * 64;
#pragma unroll
            for (int i = 0; i < 4; i++) {
                int c = tid + 256 * i;
                int row = c >> 3, c16 = c & 7;
                uint32_t so = SWZ128((uint32_t)(row * 128 + c16 * 16));
                cpa16(slot + OFF_AHI + so, srcA + (size_t)row * 64 + c16 * 8);
            }
#pragma unroll
            for (int i = 0; i < 8; i++) {
                int c = tid + 256 * i;
                int row = c >> 3, c16 = c & 7;
                uint32_t so = SWZ128((uint32_t)(row * 128 + c16 * 16));
                cpa16(slot + OFF_B + so, srcB + (size_t)row * 64 + c16 * 8);
            }
        }
    };

    load_chunk(0); cpa_commit();
    load_chunk(1); cpa_commit();

    // per-lane ldmatrix addressing constants
    const uint32_t lrow = (uint32_t)(lid & 15);       // row within 16-row tile
    const uint32_t lcol = (uint32_t)((lid >> 4) * 16); // 0 or 16 bytes (k half)

    for (int k = 0; k < NK; k++) {
        if (k + 2 < NK) load_chunk(k + 2);
        cpa_commit();                      // keep group count uniform
        cpa_wait<2>();                     // stage k resident (this thread)
        __syncthreads();                   // publish to all threads

        const uint32_t slot = sb + (uint32_t)(k % 3) * STAGE_BYTES;
        const uint32_t aBaseHi = slot + OFF_AHI + (uint32_t)(wm * 64) * 128 + lrow * 128;
        const uint32_t aBaseLo = slot + OFF_ALO + (uint32_t)(wm * 64) * 128 + lrow * 128;
        const uint32_t bBase   = slot + OFF_B   + (uint32_t)(wn * 64) * 128 + lrow * 128;
        const uint32_t swz = ((lrow & 7u) << 4);
        const bool has_lo = (k < NKW);

#pragma unroll
        for (int ks = 0; ks < 4; ks++) {
            const uint32_t colB = (uint32_t)(ks * 32) + lcol;
            const uint32_t csw = colB ^ swz;

            uint32_t bfr[4][4];
#pragma unroll
            for (int ntp = 0; ntp < 4; ntp++)
                ldsm_x4(bfr[ntp], bBase + (uint32_t)(ntp * 16) * 128 + csw);

            uint32_t af[4][4];
#pragma unroll
            for (int mt = 0; mt < 4; mt++)
                ldsm_x4(af[mt], aBaseHi + (uint32_t)(mt * 16) * 128 + csw);
#pragma unroll
            for (int mt = 0; mt < 4; mt++)
#pragma unroll
                for (int nt = 0; nt < 8; nt++)
                    mma16816(acc[mt][nt], af[mt],
                             bfr[nt >> 1][nt & 1], bfr[nt >> 1][2 + (nt & 1)]);

            if (has_lo) {
#pragma unroll
                for (int mt = 0; mt < 4; mt++)
                    ldsm_x4(af[mt], aBaseLo + (uint32_t)(mt * 16) * 128 + csw);
#pragma unroll
                for (int mt = 0; mt < 4; mt++)
#pragma unroll
                    for (int nt = 0; nt < 8; nt++)
                        mma16816(acc[mt][nt], af[mt],
                                 bfr[nt >> 1][nt & 1], bfr[nt >> 1][2 + (nt & 1)]);
            }
        }
        __syncthreads();                   // done reading slot before overwrite
    }

    // Epilogue: direct fp32 stores (32B-sector aligned float2 per lane).
    const int rBase = m0 + wm * 64 + (lid >> 2);
    const int cBase = n0 + wn * 64 + (lid & 3) * 2;
#pragma unroll
    for (int mt = 0; mt < 4; mt++) {
#pragma unroll
        for (int nt = 0; nt < 8; nt++) {
            float* p0 = out + (size_t)(rBase + mt * 16) * NDIM + cBase + nt * 8;
            float* p1 = out + (size_t)(rBase + mt * 16 + 8) * NDIM + cBase + nt * 8;
            *reinterpret_cast<float2*>(p0) = make_float2(acc[mt][nt][0], acc[mt][nt][1]);
            *reinterpret_cast<float2*>(p1) = make_float2(acc[mt][nt][2], acc[mt][nt][3]);
        }
    }
}

// ---------------- launch -----------------------------------------------------

extern "C" void kernel_launch(void* const* d_in, const int* in_sizes, int n_in,
                              void* d_out, int out_size) {
    (void)in_sizes; (void)n_in; (void)out_size;
    const float* x  = (const float*)d_in[0];
    const int*   wi = (const int*)d_in[1];
    const float* ws = (const float*)d_in[2];
    const float* lA = (const float*)d_in[3];
    const float* lB = (const float*)d_in[4];
    float* out = (float*)d_out;

    cudaFuncSetAttribute(k_gemm, cudaFuncAttributeMaxDynamicSharedMemorySize, SMEM_ALLOC);

    k_convert_w<<<(NDIM * (size_t)KDIM) / (256 * 4), 256>>>(wi);
    k_split_x  <<<(MDIM * (size_t)KDIM) / (256 * 4), 256>>>(x, ws);
    k_lora_t   <<<MDIM / 8, 256>>>(x, lA);
    k_pad_b    <<<(NDIM * 64) / 256, 256>>>(lB);
    k_gemm     <<<(MDIM / TBM) * (NDIM / TBN), 256, SMEM_ALLOC>>>(out);
}